// round 10
// baseline (speedup 1.0000x reference)
#include <cuda_runtime.h>

// ---------------------------------------------------------------------------
// CircularRelativePositionAttention  (B=8, S=1024, D=1024, H=16, HD=64)
// Round 9: tf32 mma.sync (3-term hi/lo split) + full fusion.
//   k_relk : P[bh,q,j] = q . rel_pos_k[j]  -> g_P            (tensor mma)
//   k_fused: scores(mma)+bias -> softmax(smem) -> out = attn@V + Wfold@rel_v
//            with attn living entirely in shared memory (no g_attn).
// ---------------------------------------------------------------------------

#define Sn     1024
#define SMASK  1023
#define JPn    520
#define SCALE  0.125f
#define SSTRIDE 1032          // padded stride of the 32x1024 attn tile in smem

__device__ float g_P[(size_t)128 * Sn * JPn];   // ~272 MB bias table

// ---- tf32 helpers ---------------------------------------------------------
__device__ __forceinline__ unsigned f2tf(float x) {
    unsigned r; asm("cvt.rna.tf32.f32 %0, %1;" : "=r"(r) : "f"(x)); return r;
}
__device__ __forceinline__ void mma8(float* c, const unsigned* a, const unsigned* b) {
    asm volatile(
        "mma.sync.aligned.m16n8k8.row.col.f32.tf32.tf32.f32 "
        "{%0,%1,%2,%3},{%4,%5,%6,%7},{%8,%9},{%0,%1,%2,%3};"
        : "+f"(c[0]), "+f"(c[1]), "+f"(c[2]), "+f"(c[3])
        : "r"(a[0]), "r"(a[1]), "r"(a[2]), "r"(a[3]), "r"(b[0]), "r"(b[1]));
}
__device__ __forceinline__ void splitf4(float4 f, float4& hi, float4& lo) {
    hi.x = __uint_as_float(f2tf(f.x)); lo.x = __uint_as_float(f2tf(f.x - hi.x));
    hi.y = __uint_as_float(f2tf(f.y)); lo.y = __uint_as_float(f2tf(f.y - hi.y));
    hi.z = __uint_as_float(f2tf(f.z)); lo.z = __uint_as_float(f2tf(f.z - hi.z));
    hi.w = __uint_as_float(f2tf(f.w)); lo.w = __uint_as_float(f2tf(f.w - hi.w));
}

// ---------------------------------------------------------------------------
// Kernel 1: P[bh,q,j] = q_row . rel_pos_k[j]   (M=131072, N=513, K=64)
// block: 32 rows x 128 cols, 256 thr. warp: m16 tile (w&1), 4 n8 tiles.
// ---------------------------------------------------------------------------
__global__ void __launch_bounds__(256) k_relk(const float* __restrict__ query,
                                              const float* __restrict__ relk) {
    extern __shared__ float sm[];
    float* sQh = sm;            // 32 x 68
    float* sQl = sm + 2176;
    float* sBh = sm + 4352;     // 128 x 68
    float* sBl = sm + 13056;

    const int jt = blockIdx.x, mt = blockIdx.y;
    const int tid = threadIdx.x, w = tid >> 5, lane = tid & 31;
    const int g = lane >> 2, t4 = lane & 3;
    const int bh = (mt * 32) >> 10, q0 = (mt * 32) & SMASK;
    const int b = bh >> 4, h = bh & 15;

    for (int i = tid; i < 32 * 16; i += 256) {
        int r = i >> 4, v = i & 15;
        float4 f = *(const float4*)&query[((size_t)(b * Sn + q0 + r)) * 1024 + h * 64 + 4 * v];
        float4 hi, lo; splitf4(f, hi, lo);
        *(float4*)&sQh[r * 68 + 4 * v] = hi;
        *(float4*)&sQl[r * 68 + 4 * v] = lo;
    }
    for (int i = tid; i < 128 * 16; i += 256) {
        int r = i >> 4, v = i & 15;
        int j = jt * 128 + r;
        float4 f = make_float4(0.f, 0.f, 0.f, 0.f);
        if (j < 513) f = *(const float4*)&relk[j * 64 + 4 * v];
        float4 hi, lo; splitf4(f, hi, lo);
        *(float4*)&sBh[r * 68 + 4 * v] = hi;
        *(float4*)&sBl[r * 68 + 4 * v] = lo;
    }
    __syncthreads();

    const int mo = (w & 1) * 16, nb = (w >> 1) * 32;

    unsigned ah[8][4], al[8][4];
#pragma unroll
    for (int k8 = 0; k8 < 8; k8++) {
        int r0 = (mo + g) * 68, r1 = (mo + g + 8) * 68, c0 = k8 * 8 + t4;
        ah[k8][0] = __float_as_uint(sQh[r0 + c0]);
        ah[k8][1] = __float_as_uint(sQh[r1 + c0]);
        ah[k8][2] = __float_as_uint(sQh[r0 + c0 + 4]);
        ah[k8][3] = __float_as_uint(sQh[r1 + c0 + 4]);
        al[k8][0] = __float_as_uint(sQl[r0 + c0]);
        al[k8][1] = __float_as_uint(sQl[r1 + c0]);
        al[k8][2] = __float_as_uint(sQl[r0 + c0 + 4]);
        al[k8][3] = __float_as_uint(sQl[r1 + c0 + 4]);
    }

    float C[4][4] = {};
#pragma unroll
    for (int k8 = 0; k8 < 8; k8++) {
        unsigned bhr[4][2], blr[4][2];
#pragma unroll
        for (int n = 0; n < 4; n++) {
            int nr = (nb + n * 8 + g) * 68, kc = k8 * 8 + t4;
            bhr[n][0] = __float_as_uint(sBh[nr + kc]);
            bhr[n][1] = __float_as_uint(sBh[nr + kc + 4]);
            blr[n][0] = __float_as_uint(sBl[nr + kc]);
            blr[n][1] = __float_as_uint(sBl[nr + kc + 4]);
        }
#pragma unroll
        for (int n = 0; n < 4; n++) {
            mma8(C[n], ah[k8], bhr[n]);
            mma8(C[n], ah[k8], blr[n]);
            mma8(C[n], al[k8], bhr[n]);
        }
    }
#pragma unroll
    for (int n = 0; n < 4; n++) {
        int col = jt * 128 + nb + n * 8 + 2 * t4;
        if (col < 519) {                               // JPn pad absorbs 513..519
            size_t rowA = ((size_t)bh * Sn + q0 + mo + g) * JPn;
            *(float2*)&g_P[rowA + col] = make_float2(C[n][0], C[n][1]);
            *(float2*)&g_P[rowA + 8 * JPn + col] = make_float2(C[n][2], C[n][3]);
        }
    }
}

// ---------------------------------------------------------------------------
// Kernel 2 (fused): per (bh, 32 q rows)
//   phase1: scores = scale*QK^T + P[q,idx]  -> sS (32x1032 f32)
//   phase2: softmax in smem
//   phase3: Co  = attn @ V          (mma, 3-term split)
//   phase4: Co += Wfold @ rel_pos_v (Wfold gathered from sS), store out
// ---------------------------------------------------------------------------
#define U0 33024   // floats: end of sS
#define FUSED_SMEM_FLOATS (U0 + 21760)

__global__ void __launch_bounds__(256, 1)
k_fused(const float* __restrict__ query, const float* __restrict__ key,
        const float* __restrict__ value, const float* __restrict__ relv,
        float* __restrict__ out) {
    extern __shared__ float sm[];
    float* sS = sm;                              // 32 x 1032

    const int bh = blockIdx.y, b = bh >> 4, h = bh & 15;
    const int q0 = blockIdx.x * 32;
    const int tid = threadIdx.x, w = tid >> 5, lane = tid & 31;
    const int g = lane >> 2, t4 = lane & 3;
    const int mo = (w & 1) * 16;

    // ---------------- phase 0: load Q (hi/lo split) ----------------
    {
        float* sQh = sm + U0;            // 32 x 68
        float* sQl = sm + U0 + 2176;
        for (int i = tid; i < 32 * 16; i += 256) {
            int r = i >> 4, v = i & 15;
            float4 f = *(const float4*)&query[((size_t)(b * Sn + q0 + r)) * 1024 + h * 64 + 4 * v];
            float4 hi, lo; splitf4(f, hi, lo);
            *(float4*)&sQh[r * 68 + 4 * v] = hi;
            *(float4*)&sQl[r * 68 + 4 * v] = lo;
        }
    }
    __syncthreads();

    // cache this warp's Q fragments in registers (used for all 8 key chunks)
    unsigned ah[8][4], al[8][4];
    {
        const float* sQh = sm + U0;
        const float* sQl = sm + U0 + 2176;
#pragma unroll
        for (int k8 = 0; k8 < 8; k8++) {
            int r0 = (mo + g) * 68, r1 = (mo + g + 8) * 68, c0 = k8 * 8 + t4;
            ah[k8][0] = __float_as_uint(sQh[r0 + c0]);
            ah[k8][1] = __float_as_uint(sQh[r1 + c0]);
            ah[k8][2] = __float_as_uint(sQh[r0 + c0 + 4]);
            ah[k8][3] = __float_as_uint(sQh[r1 + c0 + 4]);
            al[k8][0] = __float_as_uint(sQl[r0 + c0]);
            al[k8][1] = __float_as_uint(sQl[r1 + c0]);
            al[k8][2] = __float_as_uint(sQl[r0 + c0 + 4]);
            al[k8][3] = __float_as_uint(sQl[r1 + c0 + 4]);
        }
    }

    // ---------------- phase 1: scores + bias -> sS ----------------
    {
        float* sKh = sm + U0 + 4352;     // 128 x 68
        float* sKl = sm + U0 + 13056;
        const int nb1 = (w >> 1) * 32;
        const int qA = q0 + mo + g, qB = qA + 8;
        const float* PA = &g_P[((size_t)bh * Sn + qA) * JPn];
        const float* PB = &g_P[((size_t)bh * Sn + qB) * JPn];

        for (int kt = 0; kt < 8; kt++) {
            if (kt) __syncthreads();
            for (int i = tid; i < 128 * 16; i += 256) {
                int r = i >> 4, v = i & 15;
                float4 f = *(const float4*)&key[((size_t)(b * Sn + kt * 128 + r)) * 1024 + h * 64 + 4 * v];
                float4 hi, lo; splitf4(f, hi, lo);
                *(float4*)&sKh[r * 68 + 4 * v] = hi;
                *(float4*)&sKl[r * 68 + 4 * v] = lo;
            }
            __syncthreads();

            float C[4][4] = {};
#pragma unroll
            for (int k8 = 0; k8 < 8; k8++) {
                unsigned bhr[4][2], blr[4][2];
#pragma unroll
                for (int n = 0; n < 4; n++) {
                    int nr = (nb1 + n * 8 + g) * 68, kc = k8 * 8 + t4;
                    bhr[n][0] = __float_as_uint(sKh[nr + kc]);
                    bhr[n][1] = __float_as_uint(sKh[nr + kc + 4]);
                    blr[n][0] = __float_as_uint(sKl[nr + kc]);
                    blr[n][1] = __float_as_uint(sKl[nr + kc + 4]);
                }
#pragma unroll
                for (int n = 0; n < 4; n++) {
                    mma8(C[n], ah[k8], bhr[n]);
                    mma8(C[n], ah[k8], blr[n]);
                    mma8(C[n], al[k8], bhr[n]);
                }
            }
            // epilogue: scale + circular-relative bias, store to sS
#pragma unroll
            for (int n = 0; n < 4; n++) {
                int c0 = kt * 128 + nb1 + n * 8 + 2 * t4;
                int c1 = c0 + 1;
                int dd, idx;
                dd = (qA - c0) & SMASK; idx = min(dd, 1024 - dd);
                sS[(mo + g) * SSTRIDE + c0] = C[n][0] * SCALE + PA[idx];
                dd = (qA - c1) & SMASK; idx = min(dd, 1024 - dd);
                sS[(mo + g) * SSTRIDE + c1] = C[n][1] * SCALE + PA[idx];
                dd = (qB - c0) & SMASK; idx = min(dd, 1024 - dd);
                sS[(mo + g + 8) * SSTRIDE + c0] = C[n][2] * SCALE + PB[idx];
                dd = (qB - c1) & SMASK; idx = min(dd, 1024 - dd);
                sS[(mo + g + 8) * SSTRIDE + c1] = C[n][3] * SCALE + PB[idx];
            }
        }
    }
    __syncthreads();

    // ---------------- phase 2: softmax in smem ----------------
    for (int r = w; r < 32; r += 8) {
        float* rowp = sS + r * SSTRIDE;
        float m = -1e30f;
        for (int k = lane; k < Sn; k += 32) m = fmaxf(m, rowp[k]);
#pragma unroll
        for (int o = 16; o; o >>= 1) m = fmaxf(m, __shfl_xor_sync(0xffffffffu, m, o));
        float ssum = 0.f;
        for (int k = lane; k < Sn; k += 32) {
            float e = __expf(rowp[k] - m);
            rowp[k] = e;
            ssum += e;
        }
#pragma unroll
        for (int o = 16; o; o >>= 1) ssum += __shfl_xor_sync(0xffffffffu, ssum, o);
        float inv = 1.0f / ssum;
        for (int k = lane; k < Sn; k += 32) rowp[k] *= inv;
    }
    __syncthreads();

    // ---------------- phase 3: Co = attn @ V ----------------
    const int nb3 = (w >> 1) * 16;
    float Co[2][4] = {};
    {
        float* sVh = sm + U0;            // 64 x 72
        float* sVl = sm + U0 + 4608;
        for (int kt = 0; kt < 16; kt++) {
            __syncthreads();
            for (int i = tid; i < 64 * 16; i += 256) {
                int r = i >> 4, v = i & 15;
                float4 f = *(const float4*)&value[((size_t)(b * Sn + kt * 64 + r)) * 1024 + h * 64 + 4 * v];
                float4 hi, lo; splitf4(f, hi, lo);
                *(float4*)&sVh[r * 72 + 4 * v] = hi;
                *(float4*)&sVl[r * 72 + 4 * v] = lo;
            }
            __syncthreads();
#pragma unroll
            for (int k8 = 0; k8 < 8; k8++) {
                int c0 = kt * 64 + k8 * 8 + t4;
                float x0 = sS[(mo + g) * SSTRIDE + c0];
                float x1 = sS[(mo + g + 8) * SSTRIDE + c0];
                float x2 = sS[(mo + g) * SSTRIDE + c0 + 4];
                float x3 = sS[(mo + g + 8) * SSTRIDE + c0 + 4];
                unsigned a3h[4], a3l[4];
                a3h[0] = f2tf(x0); a3l[0] = f2tf(x0 - __uint_as_float(a3h[0]));
                a3h[1] = f2tf(x1); a3l[1] = f2tf(x1 - __uint_as_float(a3h[1]));
                a3h[2] = f2tf(x2); a3l[2] = f2tf(x2 - __uint_as_float(a3h[2]));
                a3h[3] = f2tf(x3); a3l[3] = f2tf(x3 - __uint_as_float(a3h[3]));
                unsigned b3h[2][2], b3l[2][2];
#pragma unroll
                for (int n = 0; n < 2; n++) {
                    int kk = (k8 * 8 + t4) * 72 + nb3 + n * 8 + g;
                    b3h[n][0] = __float_as_uint(sVh[kk]);
                    b3h[n][1] = __float_as_uint(sVh[kk + 4 * 72]);
                    b3l[n][0] = __float_as_uint(sVl[kk]);
                    b3l[n][1] = __float_as_uint(sVl[kk + 4 * 72]);
                }
#pragma unroll
                for (int n = 0; n < 2; n++) {
                    mma8(Co[n], a3h, b3h[n]);
                    mma8(Co[n], a3h, b3l[n]);
                    mma8(Co[n], a3l, b3h[n]);
                }
            }
        }
    }

    // ---------------- phase 4: Co += Wfold @ rel_v ----------------
    {
        float* sW  = sm + U0;            // 32 x 68 (f32 folded weights)
        float* sRh = sm + U0 + 2176;     // 64 x 72
        float* sRl = sm + U0 + 2176 + 4608;
        for (int jt = 0; jt < 9; jt++) {
            __syncthreads();
            for (int i = tid; i < 32 * 64; i += 256) {
                int r = i >> 6, c = i & 63;
                int j = jt * 64 + c, q = q0 + r;
                float wv = 0.f;
                if (j <= 512) {
                    wv = sS[r * SSTRIDE + ((q - j) & SMASK)];
                    if (j > 0 && j < 512) wv += sS[r * SSTRIDE + ((q + j) & SMASK)];
                }
                sW[r * 68 + c] = wv;
            }
            for (int i = tid; i < 64 * 16; i += 256) {
                int r = i >> 4, v = i & 15;
                int jr = jt * 64 + r;
                float4 f = make_float4(0.f, 0.f, 0.f, 0.f);
                if (jr < 513) f = *(const float4*)&relv[jr * 64 + 4 * v];
                float4 hi, lo; splitf4(f, hi, lo);
                *(float4*)&sRh[r * 72 + 4 * v] = hi;
                *(float4*)&sRl[r * 72 + 4 * v] = lo;
            }
            __syncthreads();
#pragma unroll
            for (int k8 = 0; k8 < 8; k8++) {
                int c0 = k8 * 8 + t4;
                float x0 = sW[(mo + g) * 68 + c0];
                float x1 = sW[(mo + g + 8) * 68 + c0];
                float x2 = sW[(mo + g) * 68 + c0 + 4];
                float x3 = sW[(mo + g + 8) * 68 + c0 + 4];
                unsigned a4h[4], a4l[4];
                a4h[0] = f2tf(x0); a4l[0] = f2tf(x0 - __uint_as_float(a4h[0]));
                a4h[1] = f2tf(x1); a4l[1] = f2tf(x1 - __uint_as_float(a4h[1]));
                a4h[2] = f2tf(x2); a4l[2] = f2tf(x2 - __uint_as_float(a4h[2]));
                a4h[3] = f2tf(x3); a4l[3] = f2tf(x3 - __uint_as_float(a4h[3]));
                unsigned b4h[2][2], b4l[2][2];
#pragma unroll
                for (int n = 0; n < 2; n++) {
                    int kk = (k8 * 8 + t4) * 72 + nb3 + n * 8 + g;
                    b4h[n][0] = __float_as_uint(sRh[kk]);
                    b4h[n][1] = __float_as_uint(sRh[kk + 4 * 72]);
                    b4l[n][0] = __float_as_uint(sRl[kk]);
                    b4l[n][1] = __float_as_uint(sRl[kk + 4 * 72]);
                }
#pragma unroll
                for (int n = 0; n < 2; n++) {
                    mma8(Co[n], a4h, b4h[n]);
                    mma8(Co[n], a4h, b4l[n]);
                    mma8(Co[n], a4l, b4h[n]);
                }
            }
        }
    }

    // ---------------- store output ----------------
#pragma unroll
    for (int n = 0; n < 2; n++) {
        int col = h * 64 + nb3 + n * 8 + 2 * t4;
        size_t rA = ((size_t)(b * Sn + q0 + mo + g)) * 1024 + col;
        *(float2*)&out[rA] = make_float2(Co[n][0], Co[n][1]);
        *(float2*)&out[rA + 8 * 1024] = make_float2(Co[n][2], Co[n][3]);
    }
}

// ---------------------------------------------------------------------------
// inputs: 0=query 1=key 2=value 3=rel_pos_k 4=rel_pos_v ; out = f32 (B,S,D)
// ---------------------------------------------------------------------------
extern "C" void kernel_launch(void* const* d_in, const int* in_sizes, int n_in,
                              void* d_out, int out_size) {
    const float* q  = (const float*)d_in[0];
    const float* k  = (const float*)d_in[1];
    const float* v  = (const float*)d_in[2];
    const float* rk = (const float*)d_in[3];
    const float* rv = (const float*)d_in[4];
    float* out = (float*)d_out;

    const int sm1 = 21760 * 4;                 // 87,040 B
    const int sm2 = FUSED_SMEM_FLOATS * 4;     // 219,136 B
    cudaFuncSetAttribute(k_relk,  cudaFuncAttributeMaxDynamicSharedMemorySize, sm1);
    cudaFuncSetAttribute(k_fused, cudaFuncAttributeMaxDynamicSharedMemorySize, sm2);

    k_relk <<<dim3(5, 4096), 256, sm1>>>(q, rk);
    k_fused<<<dim3(32, 128), 256, sm2>>>(q, k, v, rv, out);
}

// round 11
// speedup vs baseline: 1.3845x; 1.3845x over previous
#include <cuda_runtime.h>

// ---------------------------------------------------------------------------
// CircularRelativePositionAttention  (B=8, S=1024, D=1024, H=16, HD=64)
// Round 10: single fully-fused kernel, 512 threads, tf32 mma (3-term split).
//   per (bh, 32 q rows):
//     p1 : sS = scale * Q K^T                     (mma, 8 chunks of 128 keys)
//     p1b: sS += scatter(P),  P[q,j]=q.rel_k[j]   (mma, 5 chunks of 128 j)
//     p2 : softmax(sS) in smem
//     p3 : Co  = attn @ V                         (mma, 16 chunks of 64 rows)
//     p4 : Co += Wfold @ rel_v  (Wfold gathered from sS)
//   No global scratch at all.
// ---------------------------------------------------------------------------

#define Sn      1024
#define SMASK   1023
#define SCALE   0.125f
#define SSTRIDE 1032
#define U0      33024                       // floats: end of sS region
#define FUSED_SMEM_BYTES ((U0 + 21760) * 4) // 219,136 B

// ---- tf32 helpers ---------------------------------------------------------
__device__ __forceinline__ unsigned f2tf(float x) {
    unsigned r; asm("cvt.rna.tf32.f32 %0, %1;" : "=r"(r) : "f"(x)); return r;
}
__device__ __forceinline__ void mma8(float* c, const unsigned* a, const unsigned* b) {
    asm volatile(
        "mma.sync.aligned.m16n8k8.row.col.f32.tf32.tf32.f32 "
        "{%0,%1,%2,%3},{%4,%5,%6,%7},{%8,%9},{%0,%1,%2,%3};"
        : "+f"(c[0]), "+f"(c[1]), "+f"(c[2]), "+f"(c[3])
        : "r"(a[0]), "r"(a[1]), "r"(a[2]), "r"(a[3]), "r"(b[0]), "r"(b[1]));
}
__device__ __forceinline__ void splitf4(float4 f, float4& hi, float4& lo) {
    hi.x = __uint_as_float(f2tf(f.x)); lo.x = __uint_as_float(f2tf(f.x - hi.x));
    hi.y = __uint_as_float(f2tf(f.y)); lo.y = __uint_as_float(f2tf(f.y - hi.y));
    hi.z = __uint_as_float(f2tf(f.z)); lo.z = __uint_as_float(f2tf(f.z - hi.z));
    hi.w = __uint_as_float(f2tf(f.w)); lo.w = __uint_as_float(f2tf(f.w - hi.w));
}

// scatter one bias value P(q,j) into the two score columns it feeds
__device__ __forceinline__ void scat(float* sS, int row, int q, int j, float v) {
    if (j <= 512) {
        sS[row * SSTRIDE + ((q - j) & SMASK)] += v;
        if (j > 0 && j < 512)
            sS[row * SSTRIDE + ((q + j) & SMASK)] += v;
    }
}

__global__ void __launch_bounds__(512, 1)
k_fused(const float* __restrict__ query, const float* __restrict__ key,
        const float* __restrict__ value, const float* __restrict__ relk,
        const float* __restrict__ relv, float* __restrict__ out) {
    extern __shared__ float sm[];
    float* sS = sm;                           // 32 x 1032 scores/attn

    const int bh = blockIdx.y, b = bh >> 4, h = bh & 15;
    const int q0 = blockIdx.x * 32;
    const int tid = threadIdx.x, w = tid >> 5, lane = tid & 31;
    const int g = lane >> 2, t4 = lane & 3;
    const int mo  = (w & 1) * 16;             // m16 tile (rows mo..mo+15)
    const int nb1 = (w >> 1) * 16;            // phase1/1b: n16 within 128-chunk
    const int nb3 = (w >> 1) * 8;             // phase3/4 : n8  within 64 cols

    float* sQh = sm + U0;                     // 32 x 68
    float* sQl = sm + U0 + 2176;
    float* sKh = sm + U0 + 4352;              // 128 x 68 (reused as V/relv 64x72)
    float* sKl = sm + U0 + 13056;

    // ---------------- phase 0: load Q (hi/lo split) ----------------
    {
        int r = tid >> 4, v = tid & 15;
        float4 f = *(const float4*)&query[((size_t)(b * Sn + q0 + r)) * 1024 + h * 64 + 4 * v];
        float4 hi, lo; splitf4(f, hi, lo);
        *(float4*)&sQh[r * 68 + 4 * v] = hi;
        *(float4*)&sQl[r * 68 + 4 * v] = lo;
    }
    __syncthreads();

    // cache Q-hi fragments in registers (used in phases 1 and 1b)
    unsigned ah[8][4];
#pragma unroll
    for (int k8 = 0; k8 < 8; k8++) {
        int r0 = (mo + g) * 68, r1 = (mo + g + 8) * 68, c0 = k8 * 8 + t4;
        ah[k8][0] = __float_as_uint(sQh[r0 + c0]);
        ah[k8][1] = __float_as_uint(sQh[r1 + c0]);
        ah[k8][2] = __float_as_uint(sQh[r0 + c0 + 4]);
        ah[k8][3] = __float_as_uint(sQh[r1 + c0 + 4]);
    }

    // ---------------- phase 1: sS = scale * Q K^T ----------------
    for (int kt = 0; kt < 8; kt++) {
        if (kt) __syncthreads();
#pragma unroll
        for (int i = tid; i < 128 * 16; i += 512) {
            int r = i >> 4, v = i & 15;
            float4 f = *(const float4*)&key[((size_t)(b * Sn + kt * 128 + r)) * 1024 + h * 64 + 4 * v];
            float4 hi, lo; splitf4(f, hi, lo);
            *(float4*)&sKh[r * 68 + 4 * v] = hi;
            *(float4*)&sKl[r * 68 + 4 * v] = lo;
        }
        __syncthreads();

        float C[2][4] = {};
#pragma unroll
        for (int k8 = 0; k8 < 8; k8++) {
            int kc = k8 * 8 + t4;
            unsigned al[4];
            {
                int r0 = (mo + g) * 68, r1 = (mo + g + 8) * 68;
                al[0] = __float_as_uint(sQl[r0 + kc]);
                al[1] = __float_as_uint(sQl[r1 + kc]);
                al[2] = __float_as_uint(sQl[r0 + kc + 4]);
                al[3] = __float_as_uint(sQl[r1 + kc + 4]);
            }
#pragma unroll
            for (int n = 0; n < 2; n++) {
                int nr = (nb1 + n * 8 + g) * 68;
                unsigned bh2[2], bl2[2];
                bh2[0] = __float_as_uint(sKh[nr + kc]);
                bh2[1] = __float_as_uint(sKh[nr + kc + 4]);
                bl2[0] = __float_as_uint(sKl[nr + kc]);
                bl2[1] = __float_as_uint(sKl[nr + kc + 4]);
                mma8(C[n], ah[k8], bh2);
                mma8(C[n], ah[k8], bl2);
                mma8(C[n], al,     bh2);
            }
        }
#pragma unroll
        for (int n = 0; n < 2; n++) {
            int row = mo + g;
            int col = kt * 128 + nb1 + n * 8 + 2 * t4;
            sS[row * SSTRIDE + col]           = C[n][0] * SCALE;
            sS[row * SSTRIDE + col + 1]       = C[n][1] * SCALE;
            sS[(row + 8) * SSTRIDE + col]     = C[n][2] * SCALE;
            sS[(row + 8) * SSTRIDE + col + 1] = C[n][3] * SCALE;
        }
    }

    // ---------------- phase 1b: scatter-add bias P(q,j)=q.relk[j] ----------
    for (int jt = 0; jt < 5; jt++) {
        __syncthreads();
#pragma unroll
        for (int i = tid; i < 128 * 16; i += 512) {
            int r = i >> 4, v = i & 15;
            int j = jt * 128 + r;
            float4 f = make_float4(0.f, 0.f, 0.f, 0.f);
            if (j < 513) f = *(const float4*)&relk[j * 64 + 4 * v];
            float4 hi, lo; splitf4(f, hi, lo);
            *(float4*)&sKh[r * 68 + 4 * v] = hi;
            *(float4*)&sKl[r * 68 + 4 * v] = lo;
        }
        __syncthreads();

        float C[2][4] = {};
#pragma unroll
        for (int k8 = 0; k8 < 8; k8++) {
            int kc = k8 * 8 + t4;
            unsigned al[4];
            {
                int r0 = (mo + g) * 68, r1 = (mo + g + 8) * 68;
                al[0] = __float_as_uint(sQl[r0 + kc]);
                al[1] = __float_as_uint(sQl[r1 + kc]);
                al[2] = __float_as_uint(sQl[r0 + kc + 4]);
                al[3] = __float_as_uint(sQl[r1 + kc + 4]);
            }
#pragma unroll
            for (int n = 0; n < 2; n++) {
                int nr = (nb1 + n * 8 + g) * 68;
                unsigned bh2[2], bl2[2];
                bh2[0] = __float_as_uint(sKh[nr + kc]);
                bh2[1] = __float_as_uint(sKh[nr + kc + 4]);
                bl2[0] = __float_as_uint(sKl[nr + kc]);
                bl2[1] = __float_as_uint(sKl[nr + kc + 4]);
                mma8(C[n], ah[k8], bh2);
                mma8(C[n], ah[k8], bl2);
                mma8(C[n], al,     bh2);
            }
        }
#pragma unroll
        for (int n = 0; n < 2; n++) {
            int rowA = mo + g, qA = q0 + rowA;
            int j0 = jt * 128 + nb1 + n * 8 + 2 * t4;
            scat(sS, rowA,     qA,     j0,     C[n][0]);
            scat(sS, rowA,     qA,     j0 + 1, C[n][1]);
            scat(sS, rowA + 8, qA + 8, j0,     C[n][2]);
            scat(sS, rowA + 8, qA + 8, j0 + 1, C[n][3]);
        }
    }
    __syncthreads();

    // ---------------- phase 2: softmax in smem ----------------
    for (int r = w; r < 32; r += 16) {
        float* rowp = sS + r * SSTRIDE;
        float m = -1e30f;
        for (int k = lane; k < Sn; k += 32) m = fmaxf(m, rowp[k]);
#pragma unroll
        for (int o = 16; o; o >>= 1) m = fmaxf(m, __shfl_xor_sync(0xffffffffu, m, o));
        float ssum = 0.f;
        for (int k = lane; k < Sn; k += 32) {
            float e = __expf(rowp[k] - m);
            rowp[k] = e;
            ssum += e;
        }
#pragma unroll
        for (int o = 16; o; o >>= 1) ssum += __shfl_xor_sync(0xffffffffu, ssum, o);
        float inv = 1.0f / ssum;
        for (int k = lane; k < Sn; k += 32) rowp[k] *= inv;
    }

    // ---------------- phase 3: Co = attn @ V ----------------
    float Co[4] = {};
    {
        float* sVh = sm + U0 + 4352;          // 64 x 72
        float* sVl = sm + U0 + 4352 + 4608;
        for (int kt = 0; kt < 16; kt++) {
            __syncthreads();
#pragma unroll
            for (int i = tid; i < 64 * 16; i += 512) {
                int r = i >> 4, v = i & 15;
                float4 f = *(const float4*)&value[((size_t)(b * Sn + kt * 64 + r)) * 1024 + h * 64 + 4 * v];
                float4 hi, lo; splitf4(f, hi, lo);
                *(float4*)&sVh[r * 72 + 4 * v] = hi;
                *(float4*)&sVl[r * 72 + 4 * v] = lo;
            }
            __syncthreads();
#pragma unroll
            for (int k8 = 0; k8 < 8; k8++) {
                int c0 = kt * 64 + k8 * 8 + t4;
                float x0 = sS[(mo + g) * SSTRIDE + c0];
                float x1 = sS[(mo + g + 8) * SSTRIDE + c0];
                float x2 = sS[(mo + g) * SSTRIDE + c0 + 4];
                float x3 = sS[(mo + g + 8) * SSTRIDE + c0 + 4];
                unsigned a3h[4], a3l[4];
                a3h[0] = f2tf(x0); a3l[0] = f2tf(x0 - __uint_as_float(a3h[0]));
                a3h[1] = f2tf(x1); a3l[1] = f2tf(x1 - __uint_as_float(a3h[1]));
                a3h[2] = f2tf(x2); a3l[2] = f2tf(x2 - __uint_as_float(a3h[2]));
                a3h[3] = f2tf(x3); a3l[3] = f2tf(x3 - __uint_as_float(a3h[3]));
                int kk = (k8 * 8 + t4) * 72 + nb3 + g;
                unsigned b3h[2], b3l[2];
                b3h[0] = __float_as_uint(sVh[kk]);
                b3h[1] = __float_as_uint(sVh[kk + 4 * 72]);
                b3l[0] = __float_as_uint(sVl[kk]);
                b3l[1] = __float_as_uint(sVl[kk + 4 * 72]);
                mma8(Co, a3h, b3h);
                mma8(Co, a3h, b3l);
                mma8(Co, a3l, b3h);
            }
        }
    }

    // ---------------- phase 4: Co += Wfold @ rel_v ----------------
    {
        float* sW  = sm + U0;                 // 32 x 68 folded weights
        float* sRh = sm + U0 + 4352;          // 64 x 72
        float* sRl = sm + U0 + 4352 + 4608;
        for (int jt = 0; jt < 9; jt++) {
            __syncthreads();
#pragma unroll
            for (int i = tid; i < 32 * 64; i += 512) {
                int r = i >> 6, c = i & 63;
                int j = jt * 64 + c, q = q0 + r;
                float wv = 0.f;
                if (j <= 512) {
                    wv = sS[r * SSTRIDE + ((q - j) & SMASK)];
                    if (j > 0 && j < 512) wv += sS[r * SSTRIDE + ((q + j) & SMASK)];
                }
                sW[r * 68 + c] = wv;
            }
#pragma unroll
            for (int i = tid; i < 64 * 16; i += 512) {
                int r = i >> 4, v = i & 15;
                int jr = jt * 64 + r;
                float4 f = make_float4(0.f, 0.f, 0.f, 0.f);
                if (jr < 513) f = *(const float4*)&relv[jr * 64 + 4 * v];
                float4 hi, lo; splitf4(f, hi, lo);
                *(float4*)&sRh[r * 72 + 4 * v] = hi;
                *(float4*)&sRl[r * 72 + 4 * v] = lo;
            }
            __syncthreads();
#pragma unroll
            for (int k8 = 0; k8 < 8; k8++) {
                int c0 = k8 * 8 + t4;
                float x0 = sW[(mo + g) * 68 + c0];
                float x1 = sW[(mo + g + 8) * 68 + c0];
                float x2 = sW[(mo + g) * 68 + c0 + 4];
                float x3 = sW[(mo + g + 8) * 68 + c0 + 4];
                unsigned a4h[4], a4l[4];
                a4h[0] = f2tf(x0); a4l[0] = f2tf(x0 - __uint_as_float(a4h[0]));
                a4h[1] = f2tf(x1); a4l[1] = f2tf(x1 - __uint_as_float(a4h[1]));
                a4h[2] = f2tf(x2); a4l[2] = f2tf(x2 - __uint_as_float(a4h[2]));
                a4h[3] = f2tf(x3); a4l[3] = f2tf(x3 - __uint_as_float(a4h[3]));
                int kk = (k8 * 8 + t4) * 72 + nb3 + g;
                unsigned b4h[2], b4l[2];
                b4h[0] = __float_as_uint(sRh[kk]);
                b4h[1] = __float_as_uint(sRh[kk + 4 * 72]);
                b4l[0] = __float_as_uint(sRl[kk]);
                b4l[1] = __float_as_uint(sRl[kk + 4 * 72]);
                mma8(Co, a4h, b4h);
                mma8(Co, a4h, b4l);
                mma8(Co, a4l, b4h);
            }
        }
    }

    // ---------------- store output ----------------
    {
        int col = h * 64 + nb3 + 2 * t4;
        size_t rA = ((size_t)(b * Sn + q0 + mo + g)) * 1024 + col;
        *(float2*)&out[rA]            = make_float2(Co[0], Co[1]);
        *(float2*)&out[rA + 8 * 1024] = make_float2(Co[2], Co[3]);
    }
}

// ---------------------------------------------------------------------------
// inputs: 0=query 1=key 2=value 3=rel_pos_k 4=rel_pos_v ; out = f32 (B,S,D)
// ---------------------------------------------------------------------------
extern "C" void kernel_launch(void* const* d_in, const int* in_sizes, int n_in,
                              void* d_out, int out_size) {
    const float* q  = (const float*)d_in[0];
    const float* k  = (const float*)d_in[1];
    const float* v  = (const float*)d_in[2];
    const float* rk = (const float*)d_in[3];
    const float* rv = (const float*)d_in[4];
    float* out = (float*)d_out;

    cudaFuncSetAttribute(k_fused, cudaFuncAttributeMaxDynamicSharedMemorySize,
                         FUSED_SMEM_BYTES);
    k_fused<<<dim3(32, 128), 512, FUSED_SMEM_BYTES>>>(q, k, v, rk, rv, out);
}

// round 12
// speedup vs baseline: 2.0453x; 1.4773x over previous
#include <cuda_runtime.h>
#include <cuda_bf16.h>

// ---------------------------------------------------------------------------
// CircularRelativePositionAttention  (B=8, S=1024, D=1024, H=16, HD=64)
// Round 11: single fused kernel, bf16 mma m16n8k16 (3-term hi/lo split).
//   p0 : stage Q as bf16x2 hi/lo
//   p1 : sS = scale * Q K^T            (4 chunks x 256 keys)
//   sp : sS += P(q,512) scatter        (tiny fp32 pass)
//   p1b: sS += scatter(P(q,j)), j<512  (2 chunks x 256 j)
//   p2 : softmax(sS) fp32 in smem
//   p4 : Co  = Wfold @ rel_v           (fp32 gather -> bf16 frags)
//   cv : convert sS rows to bf16x2 hi/lo IN PLACE
//   p3 : Co += attn @ V                (pure-load bf16 frags)
// ---------------------------------------------------------------------------

#define Sn      1024
#define SMASK   1023
#define SCALE   0.125f
#define SSTRIDE 1032
#define U0      33024
#define SMEM_BYTES ((U0 + 18944) * 4)   // 207,872 B

// ---- bf16 helpers ---------------------------------------------------------
__device__ __forceinline__ void sp2(float x0, float x1, unsigned& uh, unsigned& ul) {
    __nv_bfloat162 hh = __floats2bfloat162_rn(x0, x1);   // x0 -> low half
    float l0 = x0 - __bfloat162float(hh.x);
    float l1 = x1 - __bfloat162float(hh.y);
    __nv_bfloat162 ll = __floats2bfloat162_rn(l0, l1);
    uh = *reinterpret_cast<unsigned*>(&hh);
    ul = *reinterpret_cast<unsigned*>(&ll);
}
__device__ __forceinline__ void mma16(float* c, const unsigned* a, const unsigned* b) {
    asm volatile(
        "mma.sync.aligned.m16n8k16.row.col.f32.bf16.bf16.f32 "
        "{%0,%1,%2,%3},{%4,%5,%6,%7},{%8,%9},{%0,%1,%2,%3};"
        : "+f"(c[0]), "+f"(c[1]), "+f"(c[2]), "+f"(c[3])
        : "r"(a[0]), "r"(a[1]), "r"(a[2]), "r"(a[3]), "r"(b[0]), "r"(b[1]));
}

__global__ void __launch_bounds__(512, 1)
k_fused(const float* __restrict__ query, const float* __restrict__ key,
        const float* __restrict__ value, const float* __restrict__ relk,
        const float* __restrict__ relv, float* __restrict__ out) {
    extern __shared__ float sm[];
    unsigned* su = reinterpret_cast<unsigned*>(sm);
    float* sS = sm;                                 // 32 x 1032 fp32 scores

    const int bh = blockIdx.y, b = bh >> 4, h = bh & 15;
    const int q0 = blockIdx.x * 32;
    const int tid = threadIdx.x, w = tid >> 5, lane = tid & 31;
    const int g = lane >> 2, t4 = lane & 3;
    const int mo  = (w & 1) * 16;                   // m16 tile rows
    const int nb1 = (w >> 1) * 32;                  // p1/p1b: 32 keys per warp
    const int nb3 = (w >> 1) * 8;                   // p3/p4 : n8 tile

    unsigned* q2h = su + U0;                        // 32 x 36 (pairs of head dim)
    unsigned* q2l = su + U0 + 1152;
    unsigned* k2h = su + U0 + 2304;                 // 32 kp x 260 n
    unsigned* k2l = su + U0 + 10624;

    // ---------------- p0: stage Q (hi/lo bf16x2, packed along k) -----------
    {
        int r = tid >> 4, v = tid & 15;
        const float4 f = *(const float4*)&query[((size_t)(b * Sn + q0 + r)) * 1024 + h * 64 + 4 * v];
        unsigned h0, l0, h1, l1;
        sp2(f.x, f.y, h0, l0);
        sp2(f.z, f.w, h1, l1);
        q2h[r * 36 + 2 * v] = h0; q2h[r * 36 + 2 * v + 1] = h1;
        q2l[r * 36 + 2 * v] = l0; q2l[r * 36 + 2 * v + 1] = l1;
    }
    __syncthreads();

    // cache Q fragments (4 k16 chunks)
    unsigned ah[4][4], al[4][4];
#pragma unroll
    for (int c = 0; c < 4; c++) {
        int rA = (mo + g) * 36, rB = (mo + g + 8) * 36, p = c * 8 + t4;
        ah[c][0] = q2h[rA + p];     ah[c][1] = q2h[rB + p];
        ah[c][2] = q2h[rA + p + 4]; ah[c][3] = q2h[rB + p + 4];
        al[c][0] = q2l[rA + p];     al[c][1] = q2l[rB + p];
        al[c][2] = q2l[rA + p + 4]; al[c][3] = q2l[rB + p + 4];
    }

    // ---------------- p1: sS = SCALE * Q K^T  (4 x 256 keys) ---------------
    for (int kt = 0; kt < 4; kt++) {
        __syncthreads();
#pragma unroll
        for (int i = tid; i < 256 * 16; i += 512) {
            int n = i >> 4, v = i & 15;
            const float4 f = *(const float4*)&key[((size_t)(b * Sn + kt * 256 + n)) * 1024 + h * 64 + 4 * v];
            unsigned h0, l0, h1, l1;
            sp2(f.x, f.y, h0, l0);
            sp2(f.z, f.w, h1, l1);
            k2h[(2 * v) * 260 + n] = h0; k2h[(2 * v + 1) * 260 + n] = h1;
            k2l[(2 * v) * 260 + n] = l0; k2l[(2 * v + 1) * 260 + n] = l1;
        }
        __syncthreads();

        float C[4][4] = {};
#pragma unroll
        for (int c = 0; c < 4; c++) {
#pragma unroll
            for (int t = 0; t < 4; t++) {
                int n = nb1 + t * 8 + g;
                unsigned bh2[2], bl2[2];
                bh2[0] = k2h[(c * 8 + t4) * 260 + n];
                bh2[1] = k2h[(c * 8 + t4 + 4) * 260 + n];
                bl2[0] = k2l[(c * 8 + t4) * 260 + n];
                bl2[1] = k2l[(c * 8 + t4 + 4) * 260 + n];
                mma16(C[t], ah[c], bh2);
                mma16(C[t], ah[c], bl2);
                mma16(C[t], al[c], bh2);
            }
        }
#pragma unroll
        for (int t = 0; t < 4; t++) {
            int col = kt * 256 + nb1 + t * 8 + 2 * t4;
            int ra = mo + g;
            sS[ra * SSTRIDE + col]           = C[t][0] * SCALE;
            sS[ra * SSTRIDE + col + 1]       = C[t][1] * SCALE;
            sS[(ra + 8) * SSTRIDE + col]     = C[t][2] * SCALE;
            sS[(ra + 8) * SSTRIDE + col + 1] = C[t][3] * SCALE;
        }
    }
    __syncthreads();

    // ---------------- special term: P(q,512) -> col (q+512)&1023 -----------
    {
        int r = tid >> 4, v = tid & 15;
        const float4 qf = *(const float4*)&query[((size_t)(b * Sn + q0 + r)) * 1024 + h * 64 + 4 * v];
        const float4 rf = *(const float4*)&relk[512 * 64 + 4 * v];
        float part = qf.x * rf.x + qf.y * rf.y + qf.z * rf.z + qf.w * rf.w;
#pragma unroll
        for (int o = 8; o; o >>= 1) part += __shfl_xor_sync(0xffffffffu, part, o);
        if (v == 0)
            sS[r * SSTRIDE + ((q0 + r + 512) & SMASK)] += part;
    }

    // ---------------- p1b: scatter-add bias P(q,j), j in [0,512) -----------
    for (int jt = 0; jt < 2; jt++) {
        __syncthreads();
#pragma unroll
        for (int i = tid; i < 256 * 16; i += 512) {
            int n = i >> 4, v = i & 15;
            const float4 f = *(const float4*)&relk[(jt * 256 + n) * 64 + 4 * v];
            unsigned h0, l0, h1, l1;
            sp2(f.x, f.y, h0, l0);
            sp2(f.z, f.w, h1, l1);
            k2h[(2 * v) * 260 + n] = h0; k2h[(2 * v + 1) * 260 + n] = h1;
            k2l[(2 * v) * 260 + n] = l0; k2l[(2 * v + 1) * 260 + n] = l1;
        }
        __syncthreads();

        float C[4][4] = {};
#pragma unroll
        for (int c = 0; c < 4; c++) {
#pragma unroll
            for (int t = 0; t < 4; t++) {
                int n = nb1 + t * 8 + g;
                unsigned bh2[2], bl2[2];
                bh2[0] = k2h[(c * 8 + t4) * 260 + n];
                bh2[1] = k2h[(c * 8 + t4 + 4) * 260 + n];
                bl2[0] = k2l[(c * 8 + t4) * 260 + n];
                bl2[1] = k2l[(c * 8 + t4 + 4) * 260 + n];
                mma16(C[t], ah[c], bh2);
                mma16(C[t], ah[c], bl2);
                mma16(C[t], al[c], bh2);
            }
        }
#pragma unroll
        for (int t = 0; t < 4; t++) {
            int j  = jt * 256 + nb1 + t * 8 + 2 * t4;
            int ra = mo + g, qa = q0 + ra;
            // (ra, j), (ra, j+1), (ra+8, j), (ra+8, j+1)
            sS[ra * SSTRIDE + ((qa - j) & SMASK)] += C[t][0];
            if (j > 0) sS[ra * SSTRIDE + ((qa + j) & SMASK)] += C[t][0];
            sS[ra * SSTRIDE + ((qa - j - 1) & SMASK)] += C[t][1];
            sS[ra * SSTRIDE + ((qa + j + 1) & SMASK)] += C[t][1];
            sS[(ra + 8) * SSTRIDE + ((qa + 8 - j) & SMASK)] += C[t][2];
            if (j > 0) sS[(ra + 8) * SSTRIDE + ((qa + 8 + j) & SMASK)] += C[t][2];
            sS[(ra + 8) * SSTRIDE + ((qa + 8 - j - 1) & SMASK)] += C[t][3];
            sS[(ra + 8) * SSTRIDE + ((qa + 8 + j + 1) & SMASK)] += C[t][3];
        }
    }
    __syncthreads();

    // ---------------- p2: softmax (fp32, in smem) --------------------------
    for (int r = w; r < 32; r += 16) {
        float* rowp = sS + r * SSTRIDE;
        float m = -1e30f;
        for (int k = lane; k < Sn; k += 32) m = fmaxf(m, rowp[k]);
#pragma unroll
        for (int o = 16; o; o >>= 1) m = fmaxf(m, __shfl_xor_sync(0xffffffffu, m, o));
        float ssum = 0.f;
        for (int k = lane; k < Sn; k += 32) {
            float e = __expf(rowp[k] - m);
            rowp[k] = e;
            ssum += e;
        }
#pragma unroll
        for (int o = 16; o; o >>= 1) ssum += __shfl_xor_sync(0xffffffffu, ssum, o);
        float inv = 1.0f / ssum;
        for (int k = lane; k < Sn; k += 32) rowp[k] *= inv;
    }
    __syncthreads();

    // ---------------- p4: Co = Wfold @ rel_v  (5 x 128 j) ------------------
    float Co[4] = {};
    {
        unsigned* sWh = su + U0;                    // 32 x 68 pairs
        unsigned* sWl = su + U0 + 2176;
        unsigned* r2h = su + U0 + 4352;             // 64 kp x 72 n
        unsigned* r2l = su + U0 + 8960;
        for (int jt = 0; jt < 5; jt++) {
            __syncthreads();
#pragma unroll
            for (int i = tid; i < 32 * 64; i += 512) {
                int r = i >> 6, pp = i & 63;
                int j = jt * 128 + 2 * pp, q = q0 + r;
                const float* rowp = sS + r * SSTRIDE;
                float w0 = 0.f, w1 = 0.f;
                if (j <= 512) {
                    w0 = rowp[(q - j) & SMASK];
                    if (j > 0 && j < 512) w0 += rowp[(q + j) & SMASK];
                }
                if (j + 1 <= 512) {
                    w1 = rowp[(q - j - 1) & SMASK];
                    if (j + 1 < 512) w1 += rowp[(q + j + 1) & SMASK];
                }
                unsigned uh, ul; sp2(w0, w1, uh, ul);
                sWh[r * 68 + pp] = uh;
                sWl[r * 68 + pp] = ul;
            }
#pragma unroll
            for (int i = tid; i < 64 * 16; i += 512) {
                int p = i >> 4, v = i & 15;
                int j = jt * 128 + 2 * p;
                float4 f0 = make_float4(0.f, 0.f, 0.f, 0.f), f1 = f0;
                if (j < 513)     f0 = *(const float4*)&relv[j * 64 + 4 * v];
                if (j + 1 < 513) f1 = *(const float4*)&relv[(j + 1) * 64 + 4 * v];
                unsigned h0, l0, h1, l1, h2, l2, h3, l3;
                sp2(f0.x, f1.x, h0, l0); sp2(f0.y, f1.y, h1, l1);
                sp2(f0.z, f1.z, h2, l2); sp2(f0.w, f1.w, h3, l3);
                int o = p * 72 + 4 * v;
                r2h[o] = h0; r2h[o + 1] = h1; r2h[o + 2] = h2; r2h[o + 3] = h3;
                r2l[o] = l0; r2l[o + 1] = l1; r2l[o + 2] = l2; r2l[o + 3] = l3;
            }
            __syncthreads();
#pragma unroll
            for (int c = 0; c < 8; c++) {
                int pA = c * 8 + t4;
                unsigned a4h[4], a4l[4];
                int rA = (mo + g) * 68, rB = (mo + g + 8) * 68;
                a4h[0] = sWh[rA + pA];     a4h[1] = sWh[rB + pA];
                a4h[2] = sWh[rA + pA + 4]; a4h[3] = sWh[rB + pA + 4];
                a4l[0] = sWl[rA + pA];     a4l[1] = sWl[rB + pA];
                a4l[2] = sWl[rA + pA + 4]; a4l[3] = sWl[rB + pA + 4];
                unsigned b4h[2], b4l[2];
                b4h[0] = r2h[pA * 72 + nb3 + g]; b4h[1] = r2h[(pA + 4) * 72 + nb3 + g];
                b4l[0] = r2l[pA * 72 + nb3 + g]; b4l[1] = r2l[(pA + 4) * 72 + nb3 + g];
                mma16(Co, a4h, b4h);
                mma16(Co, a4h, b4l);
                mma16(Co, a4l, b4h);
            }
        }
    }
    __syncthreads();

    // ---------------- cv: convert sS rows to bf16x2 hi/lo IN PLACE ---------
    // row r floats [r*1032, +1024) -> hi uints at [r*1032 + p], lo at [+512+p]
    for (int r = w; r < 32; r += 16) {
        unsigned* urow = su + r * SSTRIDE;
        const float* frow = sS + r * SSTRIDE;
        unsigned lobuf[16];
#pragma unroll
        for (int i = 0; i < 16; i++) {
            int p = lane + 32 * i;
            float x0 = frow[2 * p], x1 = frow[2 * p + 1];
            unsigned uh, ul; sp2(x0, x1, uh, ul);
            urow[p] = uh;
            lobuf[i] = ul;
        }
        __syncwarp();
#pragma unroll
        for (int i = 0; i < 16; i++)
            urow[512 + lane + 32 * i] = lobuf[i];
    }

    // ---------------- p3: Co += attn @ V  (4 x 256 keys) -------------------
    {
        unsigned* v2h = su + U0;                    // 128 kp x 72 n
        unsigned* v2l = su + U0 + 9216;
        for (int kt = 0; kt < 4; kt++) {
            __syncthreads();
#pragma unroll
            for (int i = tid; i < 128 * 16; i += 512) {
                int p = i >> 4, v = i & 15;
                int sq = kt * 256 + 2 * p;
                const float4 f0 = *(const float4*)&value[((size_t)(b * Sn + sq)) * 1024 + h * 64 + 4 * v];
                const float4 f1 = *(const float4*)&value[((size_t)(b * Sn + sq + 1)) * 1024 + h * 64 + 4 * v];
                unsigned h0, l0, h1, l1, h2, l2, h3, l3;
                sp2(f0.x, f1.x, h0, l0); sp2(f0.y, f1.y, h1, l1);
                sp2(f0.z, f1.z, h2, l2); sp2(f0.w, f1.w, h3, l3);
                int o = p * 72 + 4 * v;
                v2h[o] = h0; v2h[o + 1] = h1; v2h[o + 2] = h2; v2h[o + 3] = h3;
                v2l[o] = l0; v2l[o + 1] = l1; v2l[o + 2] = l2; v2l[o + 3] = l3;
            }
            __syncthreads();
#pragma unroll
            for (int s = 0; s < 16; s++) {
                int P = kt * 128 + s * 8 + t4;
                int rA = (mo + g) * SSTRIDE, rB = (mo + g + 8) * SSTRIDE;
                unsigned a3h[4], a3l[4];
                a3h[0] = su[rA + P];       a3h[1] = su[rB + P];
                a3h[2] = su[rA + P + 4];   a3h[3] = su[rB + P + 4];
                a3l[0] = su[rA + 512 + P];     a3l[1] = su[rB + 512 + P];
                a3l[2] = su[rA + 512 + P + 4]; a3l[3] = su[rB + 512 + P + 4];
                int pl = s * 8 + t4;
                unsigned b3h[2], b3l[2];
                b3h[0] = v2h[pl * 72 + nb3 + g]; b3h[1] = v2h[(pl + 4) * 72 + nb3 + g];
                b3l[0] = v2l[pl * 72 + nb3 + g]; b3l[1] = v2l[(pl + 4) * 72 + nb3 + g];
                mma16(Co, a3h, b3h);
                mma16(Co, a3h, b3l);
                mma16(Co, a3l, b3h);
            }
        }
    }

    // ---------------- store output ----------------
    {
        int col = h * 64 + nb3 + 2 * t4;
        size_t rA = ((size_t)(b * Sn + q0 + mo + g)) * 1024 + col;
        *(float2*)&out[rA]            = make_float2(Co[0], Co[1]);
        *(float2*)&out[rA + 8 * 1024] = make_float2(Co[2], Co[3]);
    }
}

// ---------------------------------------------------------------------------
// inputs: 0=query 1=key 2=value 3=rel_pos_k 4=rel_pos_v ; out = f32 (B,S,D)
// ---------------------------------------------------------------------------
extern "C" void kernel_launch(void* const* d_in, const int* in_sizes, int n_in,
                              void* d_out, int out_size) {
    const float* q  = (const float*)d_in[0];
    const float* k  = (const float*)d_in[1];
    const float* v  = (const float*)d_in[2];
    const float* rk = (const float*)d_in[3];
    const float* rv = (const float*)d_in[4];
    float* out = (float*)d_out;

    cudaFuncSetAttribute(k_fused, cudaFuncAttributeMaxDynamicSharedMemorySize,
                         SMEM_BYTES);
    k_fused<<<dim3(32, 128), 512, SMEM_BYTES>>>(q, k, v, rk, rv, out);
}

// round 13
// speedup vs baseline: 2.1037x; 1.0286x over previous
#include <cuda_runtime.h>
#include <cuda_bf16.h>

// ---------------------------------------------------------------------------
// CircularRelativePositionAttention  (B=8, S=1024, D=1024, H=16, HD=64)
// Round 12: fused bf16-mma kernel, k-split warp tiling, conflict-free smem.
// ---------------------------------------------------------------------------

#define Sn    1024
#define SMASK 1023
#define SCALE 0.125f
#define SST   1028                 // sS row stride, 1028 % 32 == 4
#define U0    32896                // 32*1028 floats = scores region
// staging offsets (floats after U0):
//  p1:  k2h 0 (256*36), k2l 9216, q2h 18432 (32*36), q2l 19584  -> 20736
//  p4:  sWh 0 (32*100), sWl 3200, r2h 6400 (64*100), r2l 12800  -> 19200
//  p3:  v2h 0 (64*132), v2l 8448                                 -> 16896
//  RED: 0..16384 (16 warps * 32 slots * 32 lanes)
#define OFF_W512 (U0 + 20736)
#define OFF_INV  (U0 + 20768)
#define OFF_RV5  (U0 + 20800)
#define SMEM_FLOATS (U0 + 20864)
#define SMEM_BYTES (SMEM_FLOATS * 4)   // 215,040 B

// ---- bf16 helpers ---------------------------------------------------------
__device__ __forceinline__ void sp2(float x0, float x1, unsigned& uh, unsigned& ul) {
    __nv_bfloat162 hh = __floats2bfloat162_rn(x0, x1);
    float l0 = x0 - __bfloat162float(hh.x);
    float l1 = x1 - __bfloat162float(hh.y);
    __nv_bfloat162 ll = __floats2bfloat162_rn(l0, l1);
    uh = *reinterpret_cast<unsigned*>(&hh);
    ul = *reinterpret_cast<unsigned*>(&ll);
}
__device__ __forceinline__ void mma16(float* c, const unsigned* a, const unsigned* b) {
    asm volatile(
        "mma.sync.aligned.m16n8k16.row.col.f32.bf16.bf16.f32 "
        "{%0,%1,%2,%3},{%4,%5,%6,%7},{%8,%9},{%0,%1,%2,%3};"
        : "+f"(c[0]), "+f"(c[1]), "+f"(c[2]), "+f"(c[3])
        : "r"(a[0]), "r"(a[1]), "r"(a[2]), "r"(a[3]), "r"(b[0]), "r"(b[1]));
}

__global__ void __launch_bounds__(512, 1)
k_fused(const float* __restrict__ query, const float* __restrict__ key,
        const float* __restrict__ value, const float* __restrict__ relk,
        const float* __restrict__ relv, float* __restrict__ out) {
    extern __shared__ float sm[];
    unsigned* su = reinterpret_cast<unsigned*>(sm);
    float* sS = sm;                                 // 32 x 1028 fp32 scores

    const int bh = blockIdx.y, b = bh >> 4, h = bh & 15;
    const int q0 = blockIdx.x * 32;
    const int tid = threadIdx.x, w = tid >> 5, lane = tid & 31;
    const int g = lane >> 2, t4 = lane & 3;

    unsigned* k2h = su + U0;                        // [n][kp]  stride 36
    unsigned* k2l = su + U0 + 9216;
    unsigned* q2h = su + U0 + 18432;                // [r][kp]  stride 36
    unsigned* q2l = su + U0 + 19584;

    // ---------------- p0: stage Q + rv512 ----------------------------------
    {
        int r = tid >> 4, v = tid & 15;
        const float4 f = *(const float4*)&query[((size_t)(b * Sn + q0 + r)) * 1024 + h * 64 + 4 * v];
        unsigned h0, l0, h1, l1;
        sp2(f.x, f.y, h0, l0); sp2(f.z, f.w, h1, l1);
        q2h[r * 36 + 2 * v] = h0; q2h[r * 36 + 2 * v + 1] = h1;
        q2l[r * 36 + 2 * v] = l0; q2l[r * 36 + 2 * v + 1] = l1;
    }
    if (tid < 64) sm[OFF_RV5 + tid] = relv[512 * 64 + tid];
    __syncthreads();

    // A fragments for m32 (both halves), 4 k16 chunks
    unsigned ah2[2][4][4], al2[2][4][4];
#pragma unroll
    for (int mh = 0; mh < 2; mh++)
#pragma unroll
        for (int c = 0; c < 4; c++) {
            int rA = (mh * 16 + g) * 36, rB = (mh * 16 + g + 8) * 36, p = c * 8 + t4;
            ah2[mh][c][0] = q2h[rA + p];     ah2[mh][c][1] = q2h[rB + p];
            ah2[mh][c][2] = q2h[rA + p + 4]; ah2[mh][c][3] = q2h[rB + p + 4];
            al2[mh][c][0] = q2l[rA + p];     al2[mh][c][1] = q2l[rB + p];
            al2[mh][c][2] = q2l[rA + p + 4]; al2[mh][c][3] = q2l[rB + p + 4];
        }

    // ---------------- p1: sS = SCALE * Q K^T  (4 x 256 keys) ---------------
    for (int kt = 0; kt < 4; kt++) {
        __syncthreads();
#pragma unroll
        for (int i = tid; i < 4096; i += 512) {
            int n = i >> 4, v = i & 15;
            const float4 f = *(const float4*)&key[((size_t)(b * Sn + kt * 256 + n)) * 1024 + h * 64 + 4 * v];
            unsigned h0, l0, h1, l1;
            sp2(f.x, f.y, h0, l0); sp2(f.z, f.w, h1, l1);
            k2h[n * 36 + 2 * v] = h0; k2h[n * 36 + 2 * v + 1] = h1;
            k2l[n * 36 + 2 * v] = l0; k2l[n * 36 + 2 * v + 1] = l1;
        }
        __syncthreads();

        float C[2][2][4] = {};
#pragma unroll
        for (int c = 0; c < 4; c++) {
#pragma unroll
            for (int t = 0; t < 2; t++) {
                int n = w * 16 + t * 8 + g, p = c * 8 + t4;
                unsigned bh2[2], bl2[2];
                bh2[0] = k2h[n * 36 + p]; bh2[1] = k2h[n * 36 + p + 4];
                bl2[0] = k2l[n * 36 + p]; bl2[1] = k2l[n * 36 + p + 4];
#pragma unroll
                for (int mh = 0; mh < 2; mh++) {
                    mma16(C[mh][t], ah2[mh][c], bh2);
                    mma16(C[mh][t], ah2[mh][c], bl2);
                    mma16(C[mh][t], al2[mh][c], bh2);
                }
            }
        }
#pragma unroll
        for (int mh = 0; mh < 2; mh++)
#pragma unroll
            for (int t = 0; t < 2; t++) {
                int col = kt * 256 + w * 16 + t * 8 + 2 * t4;
                int row = mh * 16 + g;
                *(float2*)&sS[row * SST + col] =
                    make_float2(C[mh][t][0] * SCALE, C[mh][t][1] * SCALE);
                *(float2*)&sS[(row + 8) * SST + col] =
                    make_float2(C[mh][t][2] * SCALE, C[mh][t][3] * SCALE);
            }
    }
    __syncthreads();

    // ---------------- sp: bias P(q,512) -> col (q+512)&1023 ----------------
    {
        int r = tid >> 4, v = tid & 15;
        const float4 qf = *(const float4*)&query[((size_t)(b * Sn + q0 + r)) * 1024 + h * 64 + 4 * v];
        const float4 rf = *(const float4*)&relk[512 * 64 + 4 * v];
        float part = qf.x * rf.x + qf.y * rf.y + qf.z * rf.z + qf.w * rf.w;
#pragma unroll
        for (int o = 8; o; o >>= 1) part += __shfl_xor_sync(0xffffffffu, part, o);
        if (v == 0)
            sS[r * SST + ((q0 + r + 512) & SMASK)] += part;
    }

    // ---------------- p1b: scatter-add bias P(q,j), j in [0,512) -----------
    for (int jt = 0; jt < 2; jt++) {
        __syncthreads();
#pragma unroll
        for (int i = tid; i < 4096; i += 512) {
            int n = i >> 4, v = i & 15;
            const float4 f = *(const float4*)&relk[(jt * 256 + n) * 64 + 4 * v];
            unsigned h0, l0, h1, l1;
            sp2(f.x, f.y, h0, l0); sp2(f.z, f.w, h1, l1);
            k2h[n * 36 + 2 * v] = h0; k2h[n * 36 + 2 * v + 1] = h1;
            k2l[n * 36 + 2 * v] = l0; k2l[n * 36 + 2 * v + 1] = l1;
        }
        __syncthreads();

        float C[2][2][4] = {};
#pragma unroll
        for (int c = 0; c < 4; c++) {
#pragma unroll
            for (int t = 0; t < 2; t++) {
                int n = w * 16 + t * 8 + g, p = c * 8 + t4;
                unsigned bh2[2], bl2[2];
                bh2[0] = k2h[n * 36 + p]; bh2[1] = k2h[n * 36 + p + 4];
                bl2[0] = k2l[n * 36 + p]; bl2[1] = k2l[n * 36 + p + 4];
#pragma unroll
                for (int mh = 0; mh < 2; mh++) {
                    mma16(C[mh][t], ah2[mh][c], bh2);
                    mma16(C[mh][t], ah2[mh][c], bl2);
                    mma16(C[mh][t], al2[mh][c], bh2);
                }
            }
        }
#pragma unroll
        for (int mh = 0; mh < 2; mh++)
#pragma unroll
            for (int t = 0; t < 2; t++) {
                int j = jt * 256 + w * 16 + t * 8 + 2 * t4;
#pragma unroll
                for (int rs = 0; rs < 2; rs++) {
                    int row = mh * 16 + g + 8 * rs, qa = q0 + row;
                    float c0 = C[mh][t][2 * rs], c1 = C[mh][t][2 * rs + 1];
                    sS[row * SST + ((qa - j) & SMASK)] += c0;
                    if (j > 0) sS[row * SST + ((qa + j) & SMASK)] += c0;
                    sS[row * SST + ((qa - j - 1) & SMASK)] += c1;
                    sS[row * SST + ((qa + j + 1) & SMASK)] += c1;
                }
            }
    }
    __syncthreads();

    // ---------------- p2: softmax (2-pass, exp left unnormalized) ----------
    for (int r = w; r < 32; r += 16) {
        float4* row4 = (float4*)(sS + r * SST);
        float m = -1e30f;
#pragma unroll
        for (int i = 0; i < 8; i++) {
            float4 f = row4[lane + 32 * i];
            m = fmaxf(m, fmaxf(fmaxf(f.x, f.y), fmaxf(f.z, f.w)));
        }
#pragma unroll
        for (int o = 16; o; o >>= 1) m = fmaxf(m, __shfl_xor_sync(0xffffffffu, m, o));
        float s = 0.f;
#pragma unroll
        for (int i = 0; i < 8; i++) {
            float4 f = row4[lane + 32 * i];
            f.x = __expf(f.x - m); f.y = __expf(f.y - m);
            f.z = __expf(f.z - m); f.w = __expf(f.w - m);
            row4[lane + 32 * i] = f;
            s += f.x + f.y + f.z + f.w;
        }
#pragma unroll
        for (int o = 16; o; o >>= 1) s += __shfl_xor_sync(0xffffffffu, s, o);
        if (lane == 0) {
            float inv = 1.0f / s;
            sm[OFF_INV + r] = inv;
            sm[OFF_W512 + r] = sS[r * SST + ((q0 + r + 512) & SMASK)] * inv;
        }
    }
    __syncthreads();

    // ---------------- p4: Co = Wfold @ rel_v  (k-split, 3 x 192 j) ---------
    float Co[8][4] = {};
    {
        unsigned* sWh = su + U0;                    // [r][pair] stride 100
        unsigned* sWl = su + U0 + 3200;
        unsigned* r2h = su + U0 + 6400;             // [dim][pair] stride 100
        unsigned* r2l = su + U0 + 12800;
        const int mh = w & 1, ks = w >> 1;
        for (int jt = 0; jt < 3; jt++) {
            __syncthreads();
            // Wfold gather (warp handles rows 2w, 2w+1), folded with inv
#pragma unroll
            for (int rr = 0; rr < 2; rr++) {
                int r = 2 * w + rr;
                float inv = sm[OFF_INV + r];
                int q = q0 + r;
                const float* rowp = sS + r * SST;
                for (int pp = lane; pp < 96; pp += 32) {
                    int j = jt * 192 + 2 * pp;
                    float w0 = 0.f, w1 = 0.f;
                    if (j == 0) w0 = rowp[q];
                    else if (j < 512) w0 = rowp[(q - j) & SMASK] + rowp[(q + j) & SMASK];
                    int j1 = j + 1;
                    if (j1 < 512) w1 = rowp[(q - j1) & SMASK] + rowp[(q + j1) & SMASK];
                    unsigned uh, ul; sp2(w0 * inv, w1 * inv, uh, ul);
                    sWh[r * 100 + pp] = uh;
                    sWl[r * 100 + pp] = ul;
                }
            }
            // relv staging
#pragma unroll
            for (int i = tid; i < 1536; i += 512) {
                int pr = i >> 4, v = i & 15;
                int j0 = jt * 192 + 2 * pr, j1 = j0 + 1;
                float4 f0 = make_float4(0.f, 0.f, 0.f, 0.f), f1 = f0;
                if (j0 < 512) f0 = *(const float4*)&relv[j0 * 64 + 4 * v];
                if (j1 < 512) f1 = *(const float4*)&relv[j1 * 64 + 4 * v];
                unsigned h0, l0, h1, l1, h2, l2, h3, l3;
                sp2(f0.x, f1.x, h0, l0); sp2(f0.y, f1.y, h1, l1);
                sp2(f0.z, f1.z, h2, l2); sp2(f0.w, f1.w, h3, l3);
                r2h[(4 * v) * 100 + pr] = h0; r2h[(4 * v + 1) * 100 + pr] = h1;
                r2h[(4 * v + 2) * 100 + pr] = h2; r2h[(4 * v + 3) * 100 + pr] = h3;
                r2l[(4 * v) * 100 + pr] = l0; r2l[(4 * v + 1) * 100 + pr] = l1;
                r2l[(4 * v + 2) * 100 + pr] = l2; r2l[(4 * v + 3) * 100 + pr] = l3;
            }
            __syncthreads();
#pragma unroll
            for (int c = 0; c < 12; c++) {
                if (((jt * 12 + c) & 7) != ks) continue;
                int pA = c * 8 + t4;
                int rA = (mh * 16 + g) * 100, rB = rA + 8 * 100;
                unsigned a4h[4], a4l[4];
                a4h[0] = sWh[rA + pA];     a4h[1] = sWh[rB + pA];
                a4h[2] = sWh[rA + pA + 4]; a4h[3] = sWh[rB + pA + 4];
                a4l[0] = sWl[rA + pA];     a4l[1] = sWl[rB + pA];
                a4l[2] = sWl[rA + pA + 4]; a4l[3] = sWl[rB + pA + 4];
#pragma unroll
                for (int t = 0; t < 8; t++) {
                    int n = (t * 8 + g) * 100;
                    unsigned b4h[2], b4l[2];
                    b4h[0] = r2h[n + pA]; b4h[1] = r2h[n + pA + 4];
                    b4l[0] = r2l[n + pA]; b4l[1] = r2l[n + pA + 4];
                    mma16(Co[t], a4h, b4h);
                    mma16(Co[t], a4h, b4l);
                    mma16(Co[t], a4l, b4h);
                }
            }
        }
    }
    __syncthreads();

    // ---------------- cv: sS -> bf16x2 hi/lo in place, with inv ------------
    for (int r = w; r < 32; r += 16) {
        float inv = sm[OFF_INV + r];
        unsigned* urow = su + r * SST;
        float2* row2 = (float2*)(sS + r * SST);
        unsigned lob[16];
#pragma unroll
        for (int i = 0; i < 16; i++) {
            int p = lane + 32 * i;
            float2 xv = row2[p];
            unsigned uh, ul; sp2(xv.x * inv, xv.y * inv, uh, ul);
            urow[p] = uh;
            lob[i] = ul;
        }
        __syncwarp();
#pragma unroll
        for (int i = 0; i < 16; i++)
            urow[512 + lane + 32 * i] = lob[i];
    }

    // ---------------- p3: Co += attn @ V  (k-split, 4 x 256 keys) ----------
    {
        unsigned* v2h = su + U0;                    // [dim][pair] stride 132
        unsigned* v2l = su + U0 + 8448;
        const int mh = w & 1, ks = w >> 1;
        for (int kt = 0; kt < 4; kt++) {
            __syncthreads();
#pragma unroll
            for (int i = tid; i < 2048; i += 512) {
                int pr = i >> 4, v = i & 15;
                int sq = kt * 256 + 2 * pr;
                const float4 f0 = *(const float4*)&value[((size_t)(b * Sn + sq)) * 1024 + h * 64 + 4 * v];
                const float4 f1 = *(const float4*)&value[((size_t)(b * Sn + sq + 1)) * 1024 + h * 64 + 4 * v];
                unsigned h0, l0, h1, l1, h2, l2, h3, l3;
                sp2(f0.x, f1.x, h0, l0); sp2(f0.y, f1.y, h1, l1);
                sp2(f0.z, f1.z, h2, l2); sp2(f0.w, f1.w, h3, l3);
                v2h[(4 * v) * 132 + pr] = h0; v2h[(4 * v + 1) * 132 + pr] = h1;
                v2h[(4 * v + 2) * 132 + pr] = h2; v2h[(4 * v + 3) * 132 + pr] = h3;
                v2l[(4 * v) * 132 + pr] = l0; v2l[(4 * v + 1) * 132 + pr] = l1;
                v2l[(4 * v + 2) * 132 + pr] = l2; v2l[(4 * v + 3) * 132 + pr] = l3;
            }
            __syncthreads();
#pragma unroll
            for (int c = 0; c < 16; c++) {
                if ((c & 7) != ks) continue;
                int gp = kt * 128 + c * 8 + t4;      // global key-pair
                int pl = c * 8 + t4;                 // local pair in staging
                int rA = (mh * 16 + g) * SST, rB = rA + 8 * SST;
                unsigned a3h[4], a3l[4];
                a3h[0] = su[rA + gp];       a3h[1] = su[rB + gp];
                a3h[2] = su[rA + gp + 4];   a3h[3] = su[rB + gp + 4];
                a3l[0] = su[rA + 512 + gp];     a3l[1] = su[rB + 512 + gp];
                a3l[2] = su[rA + 512 + gp + 4]; a3l[3] = su[rB + 512 + gp + 4];
#pragma unroll
                for (int t = 0; t < 8; t++) {
                    int n = (t * 8 + g) * 132;
                    unsigned b3h[2], b3l[2];
                    b3h[0] = v2h[n + pl]; b3h[1] = v2h[n + pl + 4];
                    b3l[0] = v2l[n + pl]; b3l[1] = v2l[n + pl + 4];
                    mma16(Co[t], a3h, b3h);
                    mma16(Co[t], a3h, b3l);
                    mma16(Co[t], a3l, b3h);
                }
            }
        }
    }
    __syncthreads();

    // ---------------- reduction over 8 k-splits + j=512 term + store -------
    {
        float* part = sm + U0;
#pragma unroll
        for (int t = 0; t < 8; t++)
#pragma unroll
            for (int e = 0; e < 4; e++)
                part[w * 1024 + (t * 4 + e) * 32 + lane] = Co[t][e];
    }
    __syncthreads();
    {
        float* part = sm + U0;
        const int mh = w & 1, t = w >> 1;
        float res[4];
#pragma unroll
        for (int e = 0; e < 4; e++) {
            float s = 0.f;
#pragma unroll
            for (int ks = 0; ks < 8; ks++)
                s += part[(mh + 2 * ks) * 1024 + (t * 4 + e) * 32 + lane];
            res[e] = s;
        }
        int col = t * 8 + 2 * t4;
        int row0 = mh * 16 + g;
        float w5a = sm[OFF_W512 + row0], w5b = sm[OFF_W512 + row0 + 8];
        float rv0 = sm[OFF_RV5 + col], rv1 = sm[OFF_RV5 + col + 1];
        size_t base = ((size_t)(b * Sn + q0 + row0)) * 1024 + h * 64 + col;
        *(float2*)&out[base] = make_float2(res[0] + w5a * rv0, res[1] + w5a * rv1);
        *(float2*)&out[base + 8 * 1024] = make_float2(res[2] + w5b * rv0, res[3] + w5b * rv1);
    }
}

// ---------------------------------------------------------------------------
// inputs: 0=query 1=key 2=value 3=rel_pos_k 4=rel_pos_v ; out = f32 (B,S,D)
// ---------------------------------------------------------------------------
extern "C" void kernel_launch(void* const* d_in, const int* in_sizes, int n_in,
                              void* d_out, int out_size) {
    const float* q  = (const float*)d_in[0];
    const float* k  = (const float*)d_in[1];
    const float* v  = (const float*)d_in[2];
    const float* rk = (const float*)d_in[3];
    const float* rv = (const float*)d_in[4];
    float* out = (float*)d_out;

    cudaFuncSetAttribute(k_fused, cudaFuncAttributeMaxDynamicSharedMemorySize,
                         SMEM_BYTES);
    k_fused<<<dim3(32, 128), 512, SMEM_BYTES>>>(q, k, v, rk, rv, out);
}